// round 1
// baseline (speedup 1.0000x reference)
#include <cuda_runtime.h>
#include <math.h>
#include <stdint.h>

#define LNUM 2
#define HID 512
#define TMAX 20
#define VOC 10000
#define BAT 32
#define SPA 49
#define G4 2048
#define KXH 1024
#define VLD 10240
#define NVT 40   // v-tiles of 256

// ---------------- static device scratch ----------------
__device__ float d_WcT[LNUM][KXH][G4];        // [l][k][n]  n over 4 gates
__device__ float d_WqT[HID][HID];             // [k][d]
__device__ float d_hattWT[KXH][HID];          // [k][j]
__device__ float d_projWT[HID][VLD];          // [k][v] padded
__device__ float d_keys[BAT][SPA][HID];       // keys^T
__device__ float d_vals[BAT][SPA][HID];
__device__ float d_hA[LNUM][BAT][HID];        // h entering a step
__device__ float d_hB[LNUM][BAT][HID];        // post-LSTM h
__device__ float d_cst[LNUM][BAT][HID];
__device__ float d_xh0[BAT][KXH];             // [emb | hA0]
__device__ float d_xh1[BAT][KXH];             // [hB0 | hA1]
__device__ float d_ah[LNUM*BAT][KXH];         // [attn | hB]
__device__ float d_P1[16][BAT][G4];
__device__ float d_P2[8][BAT][VLD];
__device__ float d_Pq[16][LNUM*BAT][HID];
__device__ float d_Ph[32][LNUM*BAT][HID];
__device__ float d_logits[TMAX][BAT][VOC];
__device__ float d_tmax[BAT][NVT];
__device__ int   d_tidx[BAT][NVT];

// ---------------- tiled transpose: out[c][r] = in[r][c] ----------------
__global__ void transpose_k(const float* __restrict__ in, float* __restrict__ out,
                            int R, int C, int oLd) {
    __shared__ float tile[32][33];
    int c0 = blockIdx.x * 32, r0 = blockIdx.y * 32;
    int x = threadIdx.x;
    for (int y = threadIdx.y; y < 32; y += 8) {
        int r = r0 + y, c = c0 + x;
        tile[y][x] = (r < R && c < C) ? in[(size_t)r * C + c] : 0.f;
    }
    __syncthreads();
    for (int y = threadIdx.y; y < 32; y += 8) {
        int c = c0 + y, r = r0 + x;
        if (c < C && r < R) out[(size_t)c * oLd + r] = tile[x][y];
    }
}

// ---------------- streaming GEMM partial: P[kpart][m][n] = sum_{k in chunk} A[m,k]*Bt[k,n]
template<int M, int KC>
__global__ void gemm_part(const float* __restrict__ A, int lda,
                          const float* __restrict__ Bt, int ldb, int N,
                          float* __restrict__ P, int pld) {
    __shared__ __align__(16) float As[KC][M + 4];
    int tid = threadIdx.x;
    int n = blockIdx.x * 256 + tid;
    int k0 = blockIdx.y * KC;
    for (int i = tid; i < M * KC; i += 256) {
        int m = i / KC, kk = i % KC;
        As[kk][m] = A[(size_t)m * lda + k0 + kk];
    }
    __syncthreads();
    if (n >= N) return;
    float acc[M];
#pragma unroll
    for (int m = 0; m < M; m++) acc[m] = 0.f;
    const float* bp = Bt + (size_t)k0 * ldb + n;
#pragma unroll 4
    for (int kk = 0; kk < KC; kk++) {
        float bv = bp[(size_t)kk * ldb];
#pragma unroll
        for (int m = 0; m < M; m++) acc[m] += As[kk][m] * bv;
    }
    float* pp = P + (size_t)blockIdx.y * M * pld + n;
#pragma unroll
    for (int m = 0; m < M; m++) pp[(size_t)m * pld] = acc[m];
}

// ---------------- LSTM epilogue ----------------
__global__ void lstm_act(int l, const float* __restrict__ bih, const float* __restrict__ bhh) {
    int b = blockIdx.x;
    int j = blockIdx.y * 256 + threadIdx.x;
    float g[4];
#pragma unroll
    for (int gi = 0; gi < 4; gi++) {
        float s = bih[l * G4 + gi * HID + j] + bhh[l * G4 + gi * HID + j];
#pragma unroll
        for (int p = 0; p < 16; p++) s += d_P1[p][b][gi * HID + j];
        g[gi] = s;
    }
    float i_ = 1.f / (1.f + expf(-g[0]));
    float f_ = 1.f / (1.f + expf(-g[1]));
    float gg = tanhf(g[2]);
    float o_ = 1.f / (1.f + expf(-g[3]));
    float c2 = f_ * d_cst[l][b][j] + i_ * gg;
    float h2 = o_ * tanhf(c2);
    d_cst[l][b][j] = c2;
    d_hB[l][b][j] = h2;
    if (l == 0) d_xh1[b][j] = h2;
    d_ah[l * BAT + b][HID + j] = h2;
}

// ---------------- proj combine: logits + per-tile (max, idx) ----------------
__global__ void proj_combine(int t, const float* __restrict__ projb) {
    int b = blockIdx.y, tid = threadIdx.x;
    int v = blockIdx.x * 256 + tid;
    float val = -3.4e38f;
    if (v < VOC) {
        float s = projb[v];
#pragma unroll
        for (int p = 0; p < 8; p++) s += d_P2[p][b][v];
        d_logits[t][b][v] = s;
        val = s;
    }
    __shared__ float sm[256];
    __shared__ int si[256];
    sm[tid] = val; si[tid] = v;
    __syncthreads();
    for (int off = 128; off; off >>= 1) {
        if (tid < off) {
            float ov = sm[tid + off]; int oi = si[tid + off];
            if (ov > sm[tid] || (ov == sm[tid] && oi < si[tid])) { sm[tid] = ov; si[tid] = oi; }
        }
        __syncthreads();
    }
    if (!tid) { d_tmax[b][blockIdx.x] = sm[0]; d_tidx[b][blockIdx.x] = si[0]; }
}

__global__ void argmax_gather(const float* __restrict__ embed) {
    int b = blockIdx.x, tid = threadIdx.x;
    __shared__ int best;
    if (tid == 0) {
        float mx = d_tmax[b][0]; int bi = d_tidx[b][0];
        for (int i = 1; i < NVT; i++) {
            float v = d_tmax[b][i];
            if (v > mx) { mx = v; bi = d_tidx[b][i]; }
        }
        best = bi;
    }
    __syncthreads();
    int idx = best;
    for (int j = tid; j < HID; j += 256) d_xh0[b][j] = embed[(size_t)idx * HID + j];
}

// ---------------- fused q-epilogue + scores + softmax + attn ----------------
__global__ void attn_kernel(const float* __restrict__ bq) {
    int r = blockIdx.x;
    int b = r % BAT;
    int tid = threadIdx.x;
    __shared__ float qs[HID];
    __shared__ float ws[SPA];
    for (int d = tid; d < HID; d += 256) {
        float s = bq[d];
#pragma unroll
        for (int p = 0; p < 16; p++) s += d_Pq[p][r][d];
        qs[d] = tanhf(s);
    }
    __syncthreads();
    int warp = tid >> 5, lane = tid & 31;
    for (int s = warp; s < SPA; s += 8) {
        float acc = 0.f;
        const float* kp = &d_keys[b][s][0];
        for (int k = lane; k < HID; k += 32) acc += qs[k] * kp[k];
        for (int o = 16; o; o >>= 1) acc += __shfl_xor_sync(0xffffffffu, acc, o);
        if (!lane) ws[s] = acc * (1.f / 7.f);
    }
    __syncthreads();
    if (tid == 0) {
        float mx = ws[0];
        for (int s = 1; s < SPA; s++) mx = fmaxf(mx, ws[s]);
        float sum = 0.f;
        for (int s = 0; s < SPA; s++) { float e = expf(ws[s] - mx); ws[s] = e; sum += e; }
        float inv = 1.f / sum;
        for (int s = 0; s < SPA; s++) ws[s] *= inv;
    }
    __syncthreads();
    for (int d = tid; d < HID; d += 256) {
        float a = 0.f;
#pragma unroll
        for (int s = 0; s < SPA; s++) a += ws[s] * d_vals[b][s][d];
        d_ah[r][d] = a;
    }
}

__global__ void hatt_act(const float* __restrict__ hattb) {
    int r = blockIdx.x;
    int l = r / BAT, b = r % BAT;
    int j = blockIdx.y * 256 + threadIdx.x;
    float s = hattb[j];
#pragma unroll
    for (int p = 0; p < 32; p++) s += d_Ph[p][r][j];
    float h = tanhf(s);
    d_hA[l][b][j] = h;
    if (l == 0) d_xh0[b][HID + j] = h;
    else        d_xh1[b][HID + j] = h;
}

// ---------------- keys / values precompute (transposed layout) ----------------
__global__ void kv_kernel(const float* __restrict__ chan, const float* __restrict__ Wk,
                          const float* __restrict__ bk, const float* __restrict__ Wv,
                          const float* __restrict__ bv) {
    int b = blockIdx.x;
    int d0 = blockIdx.y * 64;
    __shared__ float ct[64][SPA];
    __shared__ float wk[SPA][SPA], wv[SPA][SPA];
    __shared__ float bks[SPA], bvs[SPA];
    int tid = threadIdx.x;
    for (int i = tid; i < 64 * SPA; i += 256) {
        int d = i / SPA, s = i % SPA;
        ct[d][s] = chan[((size_t)b * HID + d0 + d) * SPA + s];
    }
    for (int i = tid; i < SPA * SPA; i += 256) {
        wk[i / SPA][i % SPA] = Wk[i];
        wv[i / SPA][i % SPA] = Wv[i];
    }
    if (tid < SPA) { bks[tid] = bk[tid]; bvs[tid] = bv[tid]; }
    __syncthreads();
    for (int i = tid; i < SPA * 64; i += 256) {
        int d = i & 63, s = i >> 6;
        float ak = bks[s], av = bvs[s];
#pragma unroll
        for (int sp = 0; sp < SPA; sp++) {
            float cv = ct[d][sp];
            ak += cv * wk[s][sp];
            av += cv * wv[s][sp];
        }
        d_keys[b][s][d0 + d] = tanhf(ak);
        d_vals[b][s][d0 + d] = tanhf(av);
    }
}

__global__ void init_kernel(const float* __restrict__ pooled, const float* __restrict__ embed,
                            const int* __restrict__ sosp) {
    int b = blockIdx.x;
    int j = blockIdx.y * 256 + threadIdx.x;
    int sos = sosp[0];
    float pv = pooled[b * HID + j];
    d_hA[0][b][j] = pv; d_hA[1][b][j] = pv;
    d_cst[0][b][j] = pv; d_cst[1][b][j] = pv;
    d_xh0[b][j] = embed[(size_t)sos * HID + j];
    d_xh0[b][HID + j] = pv;
    d_xh1[b][HID + j] = pv;
}

// res[:,:,0] — identical across batch
__global__ void logits0_kernel(const float* __restrict__ embed, const int* __restrict__ sosp,
                               const float* __restrict__ projW, const float* __restrict__ projb) {
    int warp = threadIdx.x >> 5, lane = threadIdx.x & 31;
    int v = blockIdx.x * 8 + warp;
    if (v >= VOC) return;
    int sos = sosp[0];
    const float* e = embed + (size_t)sos * HID;
    const float* w = projW + (size_t)v * HID;
    float acc = 0.f;
    for (int k = lane; k < HID; k += 32) acc += e[k] * w[k];
    for (int o = 16; o; o >>= 1) acc += __shfl_xor_sync(0xffffffffu, acc, o);
    float s = acc + projb[v];
    d_logits[0][lane][v] = s;   // all 32 lanes: lane == b
}

// ---------------- final [T][B][V] -> [B][V][T] ----------------
__global__ void out_transpose(float* __restrict__ out) {
    int b = blockIdx.x;
    int v0 = blockIdx.y * 128;
    __shared__ float tl[TMAX][129];
    int tid = threadIdx.x;
    for (int i = tid; i < TMAX * 128; i += 256) {
        int t = i >> 7, vi = i & 127;
        int v = v0 + vi;
        tl[t][vi] = (v < VOC) ? d_logits[t][b][v] : 0.f;
    }
    __syncthreads();
    for (int i = tid; i < 128 * TMAX; i += 256) {
        int vi = i / TMAX, t = i % TMAX;
        int v = v0 + vi;
        if (v < VOC) out[((size_t)b * VOC + v) * TMAX + t] = tl[t][vi];
    }
}

// ---------------- host ----------------
extern "C" void kernel_launch(void* const* d_in, const int* in_sizes, int n_in,
                              void* d_out, int out_size) {
    const float* img    = (const float*)d_in[0];
    const float* pooled = (const float*)d_in[1];
    const float* embed  = (const float*)d_in[2];
    const float* Wq     = (const float*)d_in[3];
    const float* bq     = (const float*)d_in[4];
    const float* Wk     = (const float*)d_in[5];
    const float* bk     = (const float*)d_in[6];
    const float* Wv     = (const float*)d_in[7];
    const float* bv     = (const float*)d_in[8];
    const float* Wih    = (const float*)d_in[9];
    const float* Whh    = (const float*)d_in[10];
    const float* bih    = (const float*)d_in[11];
    const float* bhh    = (const float*)d_in[12];
    const float* projW  = (const float*)d_in[13];
    const float* projb  = (const float*)d_in[14];
    const float* hattW  = (const float*)d_in[15];
    const float* hattb  = (const float*)d_in[16];
    const int*   sosp   = (const int*)d_in[17];
    float* out = (float*)d_out;

    float *pWcT, *pWqT, *pHattWT, *pProjWT, *pXh0, *pXh1, *pAh, *pHB;
    float *pP1, *pP2, *pPq, *pPh;
    cudaGetSymbolAddress((void**)&pWcT, d_WcT);
    cudaGetSymbolAddress((void**)&pWqT, d_WqT);
    cudaGetSymbolAddress((void**)&pHattWT, d_hattWT);
    cudaGetSymbolAddress((void**)&pProjWT, d_projWT);
    cudaGetSymbolAddress((void**)&pXh0, d_xh0);
    cudaGetSymbolAddress((void**)&pXh1, d_xh1);
    cudaGetSymbolAddress((void**)&pAh, d_ah);
    cudaGetSymbolAddress((void**)&pHB, d_hB);
    cudaGetSymbolAddress((void**)&pP1, d_P1);
    cudaGetSymbolAddress((void**)&pP2, d_P2);
    cudaGetSymbolAddress((void**)&pPq, d_Pq);
    cudaGetSymbolAddress((void**)&pPh, d_Ph);

    dim3 tb(32, 8);
    // Weight transposes (once per launch).  WcT[l][k<512][n]=Wih[l][n][k]; k>=512 -> Whh
    transpose_k<<<dim3(16, 64), tb>>>(Wih,                 pWcT,                        2048, 512, G4);
    transpose_k<<<dim3(16, 64), tb>>>(Whh,                 pWcT + (size_t)512 * G4,     2048, 512, G4);
    transpose_k<<<dim3(16, 64), tb>>>(Wih + 2048 * 512,    pWcT + (size_t)KXH * G4,     2048, 512, G4);
    transpose_k<<<dim3(16, 64), tb>>>(Whh + 2048 * 512,    pWcT + (size_t)KXH * G4 + (size_t)512 * G4, 2048, 512, G4);
    transpose_k<<<dim3(16, 16), tb>>>(Wq,    pWqT,    512,  512,  512);
    transpose_k<<<dim3(32, 16), tb>>>(hattW, pHattWT, 512,  1024, 512);
    transpose_k<<<dim3(16, 313), tb>>>(projW, pProjWT, VOC, 512,  VLD);

    kv_kernel<<<dim3(32, 8), 256>>>(img, Wk, bk, Wv, bv);
    init_kernel<<<dim3(32, 2), 256>>>(pooled, embed, sosp);
    logits0_kernel<<<1250, 256>>>(embed, sosp, projW, projb);

    for (int t = 0; t < TMAX - 1; t++) {
        // LSTM layer 0
        gemm_part<32, 64><<<dim3(8, 16), 256>>>(pXh0, KXH, pWcT, G4, G4, pP1, G4);
        lstm_act<<<dim3(32, 2), 256>>>(0, bih, bhh);
        // LSTM layer 1
        gemm_part<32, 64><<<dim3(8, 16), 256>>>(pXh1, KXH, pWcT + (size_t)KXH * G4, G4, G4, pP1, G4);
        lstm_act<<<dim3(32, 2), 256>>>(1, bih, bhh);
        // projection + logits + argmax tiles
        gemm_part<32, 64><<<dim3(40, 8), 256>>>(pHB + (size_t)BAT * HID, HID, pProjWT, VLD, VOC, pP2, VLD);
        proj_combine<<<dim3(40, 32), 256>>>(t + 1, projb);
        if (t < TMAX - 2) {
            argmax_gather<<<32, 256>>>(embed);
            // attention chain
            gemm_part<64, 32><<<dim3(2, 16), 256>>>(pHB, HID, pWqT, HID, HID, pPq, HID);
            attn_kernel<<<64, 256>>>(bq);
            gemm_part<64, 32><<<dim3(2, 32), 256>>>(pAh, KXH, pHattWT, HID, HID, pPh, HID);
            hatt_act<<<dim3(64, 2), 256>>>(hattb);
        }
    }

    out_transpose<<<dim3(32, 79), 256>>>(out);
    (void)in_sizes; (void)n_in; (void)out_size;
}